// round 6
// baseline (speedup 1.0000x reference)
#include <cuda_runtime.h>
#include <math.h>
#include <stdint.h>

#define T_DIM 256
#define S_DIM 2048
#define C_DIM 128
#define G3    192
#define L_DIM 64

typedef unsigned long long ull;

// Scratch gx = h_proj @ W_ih^T + b_ih, layout [t][j][s]
__device__ float g_gx[(size_t)T_DIM * G3 * S_DIM];

// ---- packed f32x2 helpers (GRU) ----
__device__ __forceinline__ ull dup2(float x) {
    ull r; asm("mov.b64 %0, {%1, %1};" : "=l"(r) : "f"(x)); return r;
}
__device__ __forceinline__ ull pack2(float x, float y) {
    ull r; asm("mov.b64 %0, {%1, %2};" : "=l"(r) : "f"(x), "f"(y)); return r;
}
__device__ __forceinline__ void fma2(ull& d, ull a, ull b) {
    asm("fma.rn.f32x2 %0, %1, %2, %0;" : "+l"(d) : "l"(a), "l"(b));
}
__device__ __forceinline__ float2 unpk(ull v) {
    float2 f; asm("mov.b64 {%0, %1}, %2;" : "=f"(f.x), "=f"(f.y) : "l"(v)); return f;
}

// ---- tf32 mma helpers (phase 1) ----
__device__ __forceinline__ uint32_t tf32b(float f) {
    uint32_t r; asm("cvt.rna.tf32.f32 %0, %1;" : "=r"(r) : "f"(f)); return r;
}
__device__ __forceinline__ float tf32f(float f) { return __uint_as_float(tf32b(f)); }

__device__ __forceinline__ void mma_tf32(float4& d,
    uint32_t a0, uint32_t a1, uint32_t a2, uint32_t a3,
    uint32_t b0, uint32_t b1)
{
    asm volatile(
      "mma.sync.aligned.m16n8k8.row.col.f32.tf32.tf32.f32 "
      "{%0,%1,%2,%3}, {%4,%5,%6,%7}, {%8,%9}, {%0,%1,%2,%3};"
      : "+f"(d.x), "+f"(d.y), "+f"(d.z), "+f"(d.w)
      : "r"(a0), "r"(a1), "r"(a2), "r"(a3), "r"(b0), "r"(b1));
}

// ---------------------------------------------------------------------------
// Phase 1 (tensor cores): each warp pushes 16 rows (t,s) through
// GEMM1 (K=128,N=32) -> lrelu -> GEMM2 (K=32,N=64) -> lrelu ->
// GEMM3 (K=64,N=192, in 3 chunks of 64) -> gx[t][j][s].
// B matrices staged in smem in fragment order Bs[(n>>3)][k][n&7]
// (bank = k*8 + n%8 -> all 32 lanes distinct). h1/h2 staged per-warp with
// row strides 36/68 -> conflict-free A-fragment loads. fp32 accumulate.
// ---------------------------------------------------------------------------
#define BS1_OFF   0            // 4 * 128 * 8 = 4096
#define BS2_OFF   4096         // 8 * 32  * 8 = 2048
#define BS3_OFF   6144         // 24 * 64 * 8 = 12288
#define B1_OFF    18432        // 32
#define B2_OFF    18464        // 64
#define BIH_OFF   18528        // 192
#define H1_OFF    18720        // 8 warps * 16*36 = 4608
#define H2_OFF    23328        // 8 warps * 16*68 = 8704
#define CHK_OFF   32032        // 8 warps * 64*20 = 10240
#define SM1_TOT   42272        // floats = 169088 B

__global__ void __launch_bounds__(256) mlp_gx_tensor(
    const float* __restrict__ x,
    const float* __restrict__ W1, const float* __restrict__ b1,
    const float* __restrict__ W2, const float* __restrict__ b2,
    const float* __restrict__ Wih, const float* __restrict__ bih)
{
    extern __shared__ float sm[];
    const int tid  = threadIdx.x;
    const int w    = tid >> 5;
    const int lane = tid & 31;
    const int gid  = lane >> 2;     // row group 0..7
    const int tig  = lane & 3;      // thread in group 0..3

    // ---- stage weights (tf32-rounded) ----
    for (int i = tid; i < 4096; i += 256) {          // W1 (128,32)
        int k = i >> 5, n = i & 31;
        sm[BS1_OFF + (n >> 3) * 1024 + k * 8 + (n & 7)] = tf32f(W1[i]);
    }
    for (int i = tid; i < 2048; i += 256) {          // W2 (32,64)
        int k = i >> 6, n = i & 63;
        sm[BS2_OFF + (n >> 3) * 256 + k * 8 + (n & 7)] = tf32f(W2[i]);
    }
    for (int i = tid; i < 12288; i += 256) {         // Wih (192,64): n=j, k
        int n = i >> 6, k = i & 63;
        sm[BS3_OFF + (n >> 3) * 512 + k * 8 + (n & 7)] = tf32f(Wih[i]);
    }
    if (tid < 32)  sm[B1_OFF + tid]  = b1[tid];
    if (tid < 64)  sm[B2_OFF + tid]  = b2[tid];
    if (tid < 192) sm[BIH_OFF + tid] = bih[tid];
    __syncthreads();

    float* h1w = sm + H1_OFF + w * (16 * 36);
    float* h2w = sm + H2_OFF + w * (16 * 68);
    float* chk = sm + CHK_OFF + w * (64 * 20);

    const int rowbase = blockIdx.x * 128 + w * 16;   // 16 rows, same t
    const int t  = rowbase >> 11;
    const int s0 = rowbase & 2047;

    // ================= GEMM1: x(16x128) @ W1(128x32) =================
    float4 acc1[4];
    #pragma unroll
    for (int nt = 0; nt < 4; nt++) {
        float bx = sm[B1_OFF + nt * 8 + 2 * tig];
        float by = sm[B1_OFF + nt * 8 + 2 * tig + 1];
        acc1[nt] = make_float4(bx, by, bx, by);
    }
    {
        const float* xr0 = x + (size_t)(rowbase + gid) * C_DIM;
        const float* xr1 = x + (size_t)(rowbase + gid + 8) * C_DIM;
        #pragma unroll
        for (int k0 = 0; k0 < 16; k0++) {
            int k = k0 * 8;
            uint32_t a0 = tf32b(__ldg(&xr0[k + tig]));
            uint32_t a1 = tf32b(__ldg(&xr1[k + tig]));
            uint32_t a2 = tf32b(__ldg(&xr0[k + tig + 4]));
            uint32_t a3 = tf32b(__ldg(&xr1[k + tig + 4]));
            #pragma unroll
            for (int nt = 0; nt < 4; nt++) {
                uint32_t bb0 = __float_as_uint(sm[BS1_OFF + nt * 1024 + (k + tig) * 8 + gid]);
                uint32_t bb1 = __float_as_uint(sm[BS1_OFF + nt * 1024 + (k + tig + 4) * 8 + gid]);
                mma_tf32(acc1[nt], a0, a1, a2, a3, bb0, bb1);
            }
        }
    }
    // lrelu + store h1 (pre-rounded to tf32)
    #pragma unroll
    for (int nt = 0; nt < 4; nt++) {
        int c = nt * 8 + 2 * tig;
        float vx = acc1[nt].x, vy = acc1[nt].y, vz = acc1[nt].z, vw = acc1[nt].w;
        h1w[gid * 36 + c]           = tf32f(fmaxf(vx, 0.01f * vx));
        h1w[gid * 36 + c + 1]       = tf32f(fmaxf(vy, 0.01f * vy));
        h1w[(gid + 8) * 36 + c]     = tf32f(fmaxf(vz, 0.01f * vz));
        h1w[(gid + 8) * 36 + c + 1] = tf32f(fmaxf(vw, 0.01f * vw));
    }
    __syncwarp();

    // ================= GEMM2: h1(16x32) @ W2(32x64) =================
    float4 acc2[8];
    #pragma unroll
    for (int nt = 0; nt < 8; nt++) {
        float bx = sm[B2_OFF + nt * 8 + 2 * tig];
        float by = sm[B2_OFF + nt * 8 + 2 * tig + 1];
        acc2[nt] = make_float4(bx, by, bx, by);
    }
    #pragma unroll
    for (int k0 = 0; k0 < 4; k0++) {
        int k = k0 * 8;
        uint32_t a0 = __float_as_uint(h1w[gid * 36 + k + tig]);
        uint32_t a1 = __float_as_uint(h1w[(gid + 8) * 36 + k + tig]);
        uint32_t a2 = __float_as_uint(h1w[gid * 36 + k + tig + 4]);
        uint32_t a3 = __float_as_uint(h1w[(gid + 8) * 36 + k + tig + 4]);
        #pragma unroll
        for (int nt = 0; nt < 8; nt++) {
            uint32_t bb0 = __float_as_uint(sm[BS2_OFF + nt * 256 + (k + tig) * 8 + gid]);
            uint32_t bb1 = __float_as_uint(sm[BS2_OFF + nt * 256 + (k + tig + 4) * 8 + gid]);
            mma_tf32(acc2[nt], a0, a1, a2, a3, bb0, bb1);
        }
    }
    #pragma unroll
    for (int nt = 0; nt < 8; nt++) {
        int c = nt * 8 + 2 * tig;
        float vx = acc2[nt].x, vy = acc2[nt].y, vz = acc2[nt].z, vw = acc2[nt].w;
        h2w[gid * 68 + c]           = tf32f(fmaxf(vx, 0.01f * vx));
        h2w[gid * 68 + c + 1]       = tf32f(fmaxf(vy, 0.01f * vy));
        h2w[(gid + 8) * 68 + c]     = tf32f(fmaxf(vz, 0.01f * vz));
        h2w[(gid + 8) * 68 + c + 1] = tf32f(fmaxf(vw, 0.01f * vw));
    }
    __syncwarp();

    // ============ GEMM3: h2(16x64) @ Wih^T(64x192), 3 chunks of 64 ============
    float* gx_t = g_gx + (size_t)t * G3 * S_DIM + s0;
    #pragma unroll 1
    for (int ch = 0; ch < 3; ch++) {
        float4 acc3[8];
        #pragma unroll
        for (int nt = 0; nt < 8; nt++) {
            float bx = sm[BIH_OFF + ch * 64 + nt * 8 + 2 * tig];
            float by = sm[BIH_OFF + ch * 64 + nt * 8 + 2 * tig + 1];
            acc3[nt] = make_float4(bx, by, bx, by);
        }
        #pragma unroll
        for (int k0 = 0; k0 < 8; k0++) {
            int k = k0 * 8;
            uint32_t a0 = __float_as_uint(h2w[gid * 68 + k + tig]);
            uint32_t a1 = __float_as_uint(h2w[(gid + 8) * 68 + k + tig]);
            uint32_t a2 = __float_as_uint(h2w[gid * 68 + k + tig + 4]);
            uint32_t a3 = __float_as_uint(h2w[(gid + 8) * 68 + k + tig + 4]);
            #pragma unroll
            for (int nt = 0; nt < 8; nt++) {
                int nb = (ch * 8 + nt) * 512;
                uint32_t bb0 = __float_as_uint(sm[BS3_OFF + nb + (k + tig) * 8 + gid]);
                uint32_t bb1 = __float_as_uint(sm[BS3_OFF + nb + (k + tig + 4) * 8 + gid]);
                mma_tf32(acc3[nt], a0, a1, a2, a3, bb0, bb1);
            }
        }
        // transpose chunk through smem: chk[col][row], stride 20
        #pragma unroll
        for (int nt = 0; nt < 8; nt++) {
            int c = nt * 8 + 2 * tig;
            chk[c * 20 + gid]             = acc3[nt].x;
            chk[(c + 1) * 20 + gid]       = acc3[nt].y;
            chk[c * 20 + gid + 8]         = acc3[nt].z;
            chk[(c + 1) * 20 + gid + 8]   = acc3[nt].w;
        }
        __syncwarp();
        // coalesced store: gx[t][ch*64 + j][s0..s0+15]
        #pragma unroll
        for (int q8 = 0; q8 < 8; q8++) {
            int j = q8 * 8 + gid;
            float4 v = *reinterpret_cast<const float4*>(&chk[j * 20 + tig * 4]);
            *reinterpret_cast<float4*>(gx_t + (size_t)(ch * 64 + j) * S_DIM + tig * 4) = v;
        }
        __syncwarp();
    }
}

// ---------------------------------------------------------------------------
// Phase 2: GRU (R3 version — best measured). 128 blocks x 384 threads,
// 16 stocks/block. Thread = (gj, stock-octet sp). Weights pre-duplicated in
// 64 registers; f32x2 pairs stocks; 2 barriers/step.
// ---------------------------------------------------------------------------
__global__ void __launch_bounds__(384, 1) gru_kernel(
    const float* __restrict__ Whh, const float* __restrict__ bhh,
    float* __restrict__ out)
{
    __shared__ float h_s[64 * 20];     // [k][s], stride 20
    __shared__ float gx_s[192 * 18];   // [j][s], stride 18
    __shared__ ull   gh_s[192 * 9];    // [g*64+j][stock-pair], stride 9

    const int tid = threadIdx.x;
    const int sp  = tid & 1;           // stock octet: stocks 8sp..8sp+7
    const int gj  = tid >> 1;          // 0..191 = g*64 + j
    const int s0  = blockIdx.x * 16;

    ull wreg[64];
    {
        const float4* wp = reinterpret_cast<const float4*>(Whh + (size_t)gj * L_DIM);
        #pragma unroll
        for (int k4 = 0; k4 < 16; k4++) {
            float4 wv = __ldg(&wp[k4]);
            wreg[k4*4+0] = dup2(wv.x);
            wreg[k4*4+1] = dup2(wv.y);
            wreg[k4*4+2] = dup2(wv.z);
            wreg[k4*4+3] = dup2(wv.w);
        }
    }
    const ull bb = dup2(__ldg(&bhh[gj]));

    for (int i = tid; i < 64 * 20; i += 384) h_s[i] = 0.0f;
    __syncthreads();

    const float* hp = h_s + 8 * sp;

    for (int t = 0; t < T_DIM; t++) {
        float gbuf[8];
        #pragma unroll
        for (int i = 0; i < 8; i++) {
            int idx = tid + 384 * i;              // 3072 = 192*16
            int jj = idx >> 4, ss = idx & 15;
            gbuf[i] = __ldg(&g_gx[((size_t)t * G3 + jj) * S_DIM + s0 + ss]);
        }

        ull a0 = bb, a1 = bb, a2 = bb, a3 = bb;
        #pragma unroll
        for (int k = 0; k < 64; k++) {
            ulonglong2 hA = *reinterpret_cast<const ulonglong2*>(hp + k * 20);
            ulonglong2 hB = *reinterpret_cast<const ulonglong2*>(hp + k * 20 + 4);
            fma2(a0, hA.x, wreg[k]);
            fma2(a1, hA.y, wreg[k]);
            fma2(a2, hB.x, wreg[k]);
            fma2(a3, hB.y, wreg[k]);
        }
        {
            ull* ghrow = gh_s + gj * 9 + sp * 4;
            ghrow[0] = a0; ghrow[1] = a1; ghrow[2] = a2; ghrow[3] = a3;
        }

        #pragma unroll
        for (int i = 0; i < 8; i++) {
            int idx = tid + 384 * i;
            int jj = idx >> 4, ss = idx & 15;
            gx_s[jj * 18 + ss] = gbuf[i];
        }
        __syncthreads();

        #pragma unroll
        for (int r = 0; r < 2; r++) {
            int q = tid + r * 384;
            if (q < 512) {
                int spg = q & 7, jq = q >> 3;
                float2 ar = unpk(gh_s[jq * 9 + spg]);
                float2 az = unpk(gh_s[(64 + jq) * 9 + spg]);
                float2 an = unpk(gh_s[(128 + jq) * 9 + spg]);
                float2 gr = unpk(*reinterpret_cast<const ull*>(gx_s + jq * 18 + 2 * spg));
                float2 gz = unpk(*reinterpret_cast<const ull*>(gx_s + (64 + jq) * 18 + 2 * spg));
                float2 gn = unpk(*reinterpret_cast<const ull*>(gx_s + (128 + jq) * 18 + 2 * spg));
                float2 ho = unpk(*reinterpret_cast<const ull*>(h_s + jq * 20 + 2 * spg));

                float hn[2];
                #pragma unroll
                for (int e = 0; e < 2; e++) {
                    float arv = e ? ar.y : ar.x, azv = e ? az.y : az.x, anv = e ? an.y : an.x;
                    float grv = e ? gr.y : gr.x, gzv = e ? gz.y : gz.x, gnv = e ? gn.y : gn.x;
                    float hov = e ? ho.y : ho.x;
                    float rr = 1.0f / (1.0f + __expf(-(grv + arv)));
                    float zz = 1.0f / (1.0f + __expf(-(gzv + azv)));
                    float narg = gnv + rr * anv;
                    float ex = __expf(-2.0f * fabsf(narg));
                    float nn = (1.0f - ex) / (1.0f + ex);
                    nn = copysignf(nn, narg);
                    hn[e] = (1.0f - zz) * nn + zz * hov;
                }
                *reinterpret_cast<ull*>(h_s + jq * 20 + 2 * spg) = pack2(hn[0], hn[1]);
            }
        }
        __syncthreads();
    }

    for (int idx = tid; idx < 1024; idx += 384) {
        int jj = idx & 63, ss = idx >> 6;
        out[(size_t)(s0 + ss) * L_DIM + jj] = h_s[jj * 20 + ss];
    }
}

// ---------------------------------------------------------------------------
extern "C" void kernel_launch(void* const* d_in, const int* in_sizes, int n_in,
                              void* d_out, int out_size)
{
    const float* x   = (const float*)d_in[0];
    const float* W1  = (const float*)d_in[1];
    const float* b1  = (const float*)d_in[2];
    const float* W2  = (const float*)d_in[3];
    const float* b2  = (const float*)d_in[4];
    const float* Wih = (const float*)d_in[5];
    const float* Whh = (const float*)d_in[6];
    const float* bih = (const float*)d_in[7];
    const float* bhh = (const float*)d_in[8];
    float* out = (float*)d_out;

    static bool attrs_set = false;
    if (!attrs_set) {
        cudaFuncSetAttribute(mlp_gx_tensor,
                             cudaFuncAttributeMaxDynamicSharedMemorySize, SM1_TOT * 4);
        attrs_set = true;
    }

    // Phase 1: 4096 blocks x 256 threads; each warp handles 16 rows
    mlp_gx_tensor<<<4096, 256, SM1_TOT * 4>>>(x, W1, b1, W2, b2, Wih, bih);
    // Phase 2: GRU
    gru_kernel<<<128, 384>>>(Whh, bhh, out);
}

// round 7
// speedup vs baseline: 1.5569x; 1.5569x over previous
#include <cuda_runtime.h>
#include <math.h>
#include <stdint.h>

#define T_DIM 256
#define S_DIM 2048
#define C_DIM 128
#define G3    192
#define L_DIM 64

typedef unsigned long long ull;

// Scratch gx = h_proj @ W_ih^T + b_ih, layout [t][j][s]
__device__ float g_gx[(size_t)T_DIM * G3 * S_DIM];

// ---- packed f32x2 helpers (GRU) ----
__device__ __forceinline__ ull dup2(float x) {
    ull r; asm("mov.b64 %0, {%1, %1};" : "=l"(r) : "f"(x)); return r;
}
__device__ __forceinline__ ull pack2(float x, float y) {
    ull r; asm("mov.b64 %0, {%1, %2};" : "=l"(r) : "f"(x), "f"(y)); return r;
}
__device__ __forceinline__ void fma2(ull& d, ull a, ull b) {
    asm("fma.rn.f32x2 %0, %1, %2, %0;" : "+l"(d) : "l"(a), "l"(b));
}
__device__ __forceinline__ float2 unpk(ull v) {
    float2 f; asm("mov.b64 {%0, %1}, %2;" : "=f"(f.x), "=f"(f.y) : "l"(v)); return f;
}

// ---- tf32 mma helpers (phase 1) ----
__device__ __forceinline__ uint32_t tf32b(float f) {
    uint32_t r; asm("cvt.rna.tf32.f32 %0, %1;" : "=r"(r) : "f"(f)); return r;
}
__device__ __forceinline__ float tf32f(float f) { return __uint_as_float(tf32b(f)); }

__device__ __forceinline__ void mma_tf32(float4& d,
    uint32_t a0, uint32_t a1, uint32_t a2, uint32_t a3,
    uint32_t b0, uint32_t b1)
{
    asm volatile(
      "mma.sync.aligned.m16n8k8.row.col.f32.tf32.tf32.f32 "
      "{%0,%1,%2,%3}, {%4,%5,%6,%7}, {%8,%9}, {%0,%1,%2,%3};"
      : "+f"(d.x), "+f"(d.y), "+f"(d.z), "+f"(d.w)
      : "r"(a0), "r"(a1), "r"(a2), "r"(a3), "r"(b0), "r"(b1));
}

// ---------------------------------------------------------------------------
// Phase 1 (tensor cores, smem-staged): block = 256 thr (8 warps), 128 rows.
// x tile staged coalesced into smem (stride 132 -> conflict-free A-frag LDS).
// Each warp: 16 rows through GEMM1(K128,N32) -> lrelu -> GEMM2(K32,N64) ->
// lrelu -> GEMM3(K64,N192 in 6 chunks of 32) -> transpose -> gx[t][j][s].
// B staged in fragment order Bs[ntile][k][n&7] (conflict-free). GEMM2/3
// A-fragments hoisted to registers. x region reused for h2/chk after barrier.
// ---------------------------------------------------------------------------
#define BS1_OFF   0            // 4 * 128 * 8 = 4096
#define BS2_OFF   4096         // 8 * 32  * 8 = 2048
#define BS3_OFF   6144         // 24 * 64 * 8 = 12288
#define B1_OFF    18432        // 32
#define B2_OFF    18464        // 64
#define BIH_OFF   18528        // 192
#define H1_OFF    18720        // 8 warps * 16*36 = 4608
#define X_OFF     23328        // 128 * 132 = 16896 (dead after GEMM1)
#define H2_OFF    23328        // 8 warps * 16*68 = 8704   (aliases X)
#define CHK_OFF   32032        // 8 warps * 32*20 = 5120   (aliases X)
#define SM1_TOT   40224        // floats = 160896 B

__global__ void __launch_bounds__(256) mlp_gx_tensor(
    const float* __restrict__ x,
    const float* __restrict__ W1, const float* __restrict__ b1,
    const float* __restrict__ W2, const float* __restrict__ b2,
    const float* __restrict__ Wih, const float* __restrict__ bih)
{
    extern __shared__ float sm[];
    const int tid  = threadIdx.x;
    const int w    = tid >> 5;
    const int lane = tid & 31;
    const int gid  = lane >> 2;     // row group 0..7
    const int tig  = lane & 3;      // thread in group 0..3

    // ---- stage weights (tf32-rounded, fragment order) ----
    for (int i = tid; i < 4096; i += 256) {          // W1 (128,32)
        int k = i >> 5, n = i & 31;
        sm[BS1_OFF + (n >> 3) * 1024 + k * 8 + (n & 7)] = tf32f(W1[i]);
    }
    for (int i = tid; i < 2048; i += 256) {          // W2 (32,64)
        int k = i >> 6, n = i & 63;
        sm[BS2_OFF + (n >> 3) * 256 + k * 8 + (n & 7)] = tf32f(W2[i]);
    }
    for (int i = tid; i < 12288; i += 256) {         // Wih (192,64): n=j, k
        int n = i >> 6, k = i & 63;
        sm[BS3_OFF + (n >> 3) * 512 + k * 8 + (n & 7)] = tf32f(Wih[i]);
    }
    if (tid < 32)  sm[B1_OFF + tid]  = b1[tid];
    if (tid < 64)  sm[B2_OFF + tid]  = b2[tid];
    if (tid < 192) sm[BIH_OFF + tid] = bih[tid];

    const int rowblock = blockIdx.x * 128;
    const int t  = rowblock >> 11;
    const int s0 = (rowblock & 2047) + w * 16;

    // ---- stage x tile: 128 rows x 128 cols, coalesced float4 ----
    {
        const float4* xg = reinterpret_cast<const float4*>(x) + (size_t)rowblock * 32;
        #pragma unroll
        for (int it = 0; it < 16; it++) {
            int fi = tid + it * 256;         // 4096 float4
            int r = fi >> 5, c4 = fi & 31;
            float4 v = __ldg(&xg[(size_t)r * 32 + c4]);
            *reinterpret_cast<float4*>(&sm[X_OFF + r * 132 + c4 * 4]) = v;
        }
    }
    __syncthreads();

    float* h1w = sm + H1_OFF + w * (16 * 36);
    const float* xw0 = sm + X_OFF + (w * 16 + 0) * 132;   // rows gid
    const float* xw8 = sm + X_OFF + (w * 16 + 8) * 132;   // rows gid+8

    // ================= GEMM1: x(16x128) @ W1(128x32) =================
    float4 acc1[4];
    #pragma unroll
    for (int nt = 0; nt < 4; nt++) {
        float bx = sm[B1_OFF + nt * 8 + 2 * tig];
        float by = sm[B1_OFF + nt * 8 + 2 * tig + 1];
        acc1[nt] = make_float4(bx, by, bx, by);
    }
    #pragma unroll
    for (int k0 = 0; k0 < 16; k0++) {
        int k = k0 * 8;
        uint32_t a0 = tf32b(xw0[gid * 132 + k + tig]);
        uint32_t a1 = tf32b(xw8[gid * 132 + k + tig]);
        uint32_t a2 = tf32b(xw0[gid * 132 + k + tig + 4]);
        uint32_t a3 = tf32b(xw8[gid * 132 + k + tig + 4]);
        #pragma unroll
        for (int nt = 0; nt < 4; nt++) {
            uint32_t bb0 = __float_as_uint(sm[BS1_OFF + nt * 1024 + (k + tig) * 8 + gid]);
            uint32_t bb1 = __float_as_uint(sm[BS1_OFF + nt * 1024 + (k + tig + 4) * 8 + gid]);
            mma_tf32(acc1[nt], a0, a1, a2, a3, bb0, bb1);
        }
    }
    // lrelu + store h1 (pre-rounded to tf32)
    #pragma unroll
    for (int nt = 0; nt < 4; nt++) {
        int c = nt * 8 + 2 * tig;
        float vx = acc1[nt].x, vy = acc1[nt].y, vz = acc1[nt].z, vw = acc1[nt].w;
        h1w[gid * 36 + c]           = tf32f(fmaxf(vx, 0.01f * vx));
        h1w[gid * 36 + c + 1]       = tf32f(fmaxf(vy, 0.01f * vy));
        h1w[(gid + 8) * 36 + c]     = tf32f(fmaxf(vz, 0.01f * vz));
        h1w[(gid + 8) * 36 + c + 1] = tf32f(fmaxf(vw, 0.01f * vw));
    }
    __syncthreads();   // all warps done reading x region -> safe to alias

    float* h2w = sm + H2_OFF + w * (16 * 68);
    float* chk = sm + CHK_OFF + w * (32 * 20);

    // ================= GEMM2: h1(16x32) @ W2(32x64) =================
    uint32_t areg2[16];
    #pragma unroll
    for (int k0 = 0; k0 < 4; k0++) {
        int k = k0 * 8;
        areg2[k0*4+0] = __float_as_uint(h1w[gid * 36 + k + tig]);
        areg2[k0*4+1] = __float_as_uint(h1w[(gid + 8) * 36 + k + tig]);
        areg2[k0*4+2] = __float_as_uint(h1w[gid * 36 + k + tig + 4]);
        areg2[k0*4+3] = __float_as_uint(h1w[(gid + 8) * 36 + k + tig + 4]);
    }
    float4 acc2[8];
    #pragma unroll
    for (int nt = 0; nt < 8; nt++) {
        float bx = sm[B2_OFF + nt * 8 + 2 * tig];
        float by = sm[B2_OFF + nt * 8 + 2 * tig + 1];
        acc2[nt] = make_float4(bx, by, bx, by);
    }
    #pragma unroll
    for (int k0 = 0; k0 < 4; k0++) {
        int k = k0 * 8;
        #pragma unroll
        for (int nt = 0; nt < 8; nt++) {
            uint32_t bb0 = __float_as_uint(sm[BS2_OFF + nt * 256 + (k + tig) * 8 + gid]);
            uint32_t bb1 = __float_as_uint(sm[BS2_OFF + nt * 256 + (k + tig + 4) * 8 + gid]);
            mma_tf32(acc2[nt], areg2[k0*4+0], areg2[k0*4+1], areg2[k0*4+2], areg2[k0*4+3], bb0, bb1);
        }
    }
    #pragma unroll
    for (int nt = 0; nt < 8; nt++) {
        int c = nt * 8 + 2 * tig;
        float vx = acc2[nt].x, vy = acc2[nt].y, vz = acc2[nt].z, vw = acc2[nt].w;
        h2w[gid * 68 + c]           = tf32f(fmaxf(vx, 0.01f * vx));
        h2w[gid * 68 + c + 1]       = tf32f(fmaxf(vy, 0.01f * vy));
        h2w[(gid + 8) * 68 + c]     = tf32f(fmaxf(vz, 0.01f * vz));
        h2w[(gid + 8) * 68 + c + 1] = tf32f(fmaxf(vw, 0.01f * vw));
    }
    __syncwarp();

    // ===== GEMM3: h2(16x64) @ Wih^T(64x192), 6 chunks of 32 columns =====
    // Hoist the h2 A-fragments (reused by all 6 chunks) into 32 registers.
    uint32_t areg3[32];
    #pragma unroll
    for (int k0 = 0; k0 < 8; k0++) {
        int k = k0 * 8;
        areg3[k0*4+0] = __float_as_uint(h2w[gid * 68 + k + tig]);
        areg3[k0*4+1] = __float_as_uint(h2w[(gid + 8) * 68 + k + tig]);
        areg3[k0*4+2] = __float_as_uint(h2w[gid * 68 + k + tig + 4]);
        areg3[k0*4+3] = __float_as_uint(h2w[(gid + 8) * 68 + k + tig + 4]);
    }

    float* gx_t = g_gx + (size_t)t * G3 * S_DIM + s0;
    #pragma unroll 1
    for (int ch = 0; ch < 6; ch++) {
        float4 acc3[4];
        #pragma unroll
        for (int nt = 0; nt < 4; nt++) {
            float bx = sm[BIH_OFF + ch * 32 + nt * 8 + 2 * tig];
            float by = sm[BIH_OFF + ch * 32 + nt * 8 + 2 * tig + 1];
            acc3[nt] = make_float4(bx, by, bx, by);
        }
        #pragma unroll
        for (int k0 = 0; k0 < 8; k0++) {
            int k = k0 * 8;
            #pragma unroll
            for (int nt = 0; nt < 4; nt++) {
                int nb = (ch * 4 + nt) * 512;
                uint32_t bb0 = __float_as_uint(sm[BS3_OFF + nb + (k + tig) * 8 + gid]);
                uint32_t bb1 = __float_as_uint(sm[BS3_OFF + nb + (k + tig + 4) * 8 + gid]);
                mma_tf32(acc3[nt], areg3[k0*4+0], areg3[k0*4+1], areg3[k0*4+2], areg3[k0*4+3], bb0, bb1);
            }
        }
        // transpose chunk through smem: chk[col][row], stride 20
        #pragma unroll
        for (int nt = 0; nt < 4; nt++) {
            int c = nt * 8 + 2 * tig;
            chk[c * 20 + gid]           = acc3[nt].x;
            chk[(c + 1) * 20 + gid]     = acc3[nt].y;
            chk[c * 20 + gid + 8]       = acc3[nt].z;
            chk[(c + 1) * 20 + gid + 8] = acc3[nt].w;
        }
        __syncwarp();
        // coalesced store: gx[t][ch*32 + j][s0..s0+15]
        #pragma unroll
        for (int q8 = 0; q8 < 4; q8++) {
            int j = q8 * 8 + gid;
            float4 v = *reinterpret_cast<const float4*>(&chk[j * 20 + tig * 4]);
            *reinterpret_cast<float4*>(gx_t + (size_t)(ch * 32 + j) * S_DIM + tig * 4) = v;
        }
        __syncwarp();
    }
}

// ---------------------------------------------------------------------------
// Phase 2: GRU (R3 version — best measured, ~710us). 128 blocks x 384 thr,
// 16 stocks/block. Weights pre-duplicated in 64 registers; f32x2 pairs stocks.
// ---------------------------------------------------------------------------
__global__ void __launch_bounds__(384, 1) gru_kernel(
    const float* __restrict__ Whh, const float* __restrict__ bhh,
    float* __restrict__ out)
{
    __shared__ float h_s[64 * 20];     // [k][s], stride 20
    __shared__ float gx_s[192 * 18];   // [j][s], stride 18
    __shared__ ull   gh_s[192 * 9];    // [g*64+j][stock-pair], stride 9

    const int tid = threadIdx.x;
    const int sp  = tid & 1;           // stock octet: stocks 8sp..8sp+7
    const int gj  = tid >> 1;          // 0..191 = g*64 + j
    const int s0  = blockIdx.x * 16;

    ull wreg[64];
    {
        const float4* wp = reinterpret_cast<const float4*>(Whh + (size_t)gj * L_DIM);
        #pragma unroll
        for (int k4 = 0; k4 < 16; k4++) {
            float4 wv = __ldg(&wp[k4]);
            wreg[k4*4+0] = dup2(wv.x);
            wreg[k4*4+1] = dup2(wv.y);
            wreg[k4*4+2] = dup2(wv.z);
            wreg[k4*4+3] = dup2(wv.w);
        }
    }
    const ull bb = dup2(__ldg(&bhh[gj]));

    for (int i = tid; i < 64 * 20; i += 384) h_s[i] = 0.0f;
    __syncthreads();

    const float* hp = h_s + 8 * sp;

    for (int t = 0; t < T_DIM; t++) {
        float gbuf[8];
        #pragma unroll
        for (int i = 0; i < 8; i++) {
            int idx = tid + 384 * i;              // 3072 = 192*16
            int jj = idx >> 4, ss = idx & 15;
            gbuf[i] = __ldg(&g_gx[((size_t)t * G3 + jj) * S_DIM + s0 + ss]);
        }

        ull a0 = bb, a1 = bb, a2 = bb, a3 = bb;
        #pragma unroll
        for (int k = 0; k < 64; k++) {
            ulonglong2 hA = *reinterpret_cast<const ulonglong2*>(hp + k * 20);
            ulonglong2 hB = *reinterpret_cast<const ulonglong2*>(hp + k * 20 + 4);
            fma2(a0, hA.x, wreg[k]);
            fma2(a1, hA.y, wreg[k]);
            fma2(a2, hB.x, wreg[k]);
            fma2(a3, hB.y, wreg[k]);
        }
        {
            ull* ghrow = gh_s + gj * 9 + sp * 4;
            ghrow[0] = a0; ghrow[1] = a1; ghrow[2] = a2; ghrow[3] = a3;
        }

        #pragma unroll
        for (int i = 0; i < 8; i++) {
            int idx = tid + 384 * i;
            int jj = idx >> 4, ss = idx & 15;
            gx_s[jj * 18 + ss] = gbuf[i];
        }
        __syncthreads();

        #pragma unroll
        for (int r = 0; r < 2; r++) {
            int q = tid + r * 384;
            if (q < 512) {
                int spg = q & 7, jq = q >> 3;
                float2 ar = unpk(gh_s[jq * 9 + spg]);
                float2 az = unpk(gh_s[(64 + jq) * 9 + spg]);
                float2 an = unpk(gh_s[(128 + jq) * 9 + spg]);
                float2 gr = unpk(*reinterpret_cast<const ull*>(gx_s + jq * 18 + 2 * spg));
                float2 gz = unpk(*reinterpret_cast<const ull*>(gx_s + (64 + jq) * 18 + 2 * spg));
                float2 gn = unpk(*reinterpret_cast<const ull*>(gx_s + (128 + jq) * 18 + 2 * spg));
                float2 ho = unpk(*reinterpret_cast<const ull*>(h_s + jq * 20 + 2 * spg));

                float hn[2];
                #pragma unroll
                for (int e = 0; e < 2; e++) {
                    float arv = e ? ar.y : ar.x, azv = e ? az.y : az.x, anv = e ? an.y : an.x;
                    float grv = e ? gr.y : gr.x, gzv = e ? gz.y : gz.x, gnv = e ? gn.y : gn.x;
                    float hov = e ? ho.y : ho.x;
                    float rr = 1.0f / (1.0f + __expf(-(grv + arv)));
                    float zz = 1.0f / (1.0f + __expf(-(gzv + azv)));
                    float narg = gnv + rr * anv;
                    float ex = __expf(-2.0f * fabsf(narg));
                    float nn = (1.0f - ex) / (1.0f + ex);
                    nn = copysignf(nn, narg);
                    hn[e] = (1.0f - zz) * nn + zz * hov;
                }
                *reinterpret_cast<ull*>(h_s + jq * 20 + 2 * spg) = pack2(hn[0], hn[1]);
            }
        }
        __syncthreads();
    }

    for (int idx = tid; idx < 1024; idx += 384) {
        int jj = idx & 63, ss = idx >> 6;
        out[(size_t)(s0 + ss) * L_DIM + jj] = h_s[jj * 20 + ss];
    }
}

// ---------------------------------------------------------------------------
extern "C" void kernel_launch(void* const* d_in, const int* in_sizes, int n_in,
                              void* d_out, int out_size)
{
    const float* x   = (const float*)d_in[0];
    const float* W1  = (const float*)d_in[1];
    const float* b1  = (const float*)d_in[2];
    const float* W2  = (const float*)d_in[3];
    const float* b2  = (const float*)d_in[4];
    const float* Wih = (const float*)d_in[5];
    const float* Whh = (const float*)d_in[6];
    const float* bih = (const float*)d_in[7];
    const float* bhh = (const float*)d_in[8];
    float* out = (float*)d_out;

    static bool attrs_set = false;
    if (!attrs_set) {
        cudaFuncSetAttribute(mlp_gx_tensor,
                             cudaFuncAttributeMaxDynamicSharedMemorySize, SM1_TOT * 4);
        attrs_set = true;
    }

    // Phase 1: 4096 blocks x 256 threads; 128 rows per block (smem-staged)
    mlp_gx_tensor<<<4096, 256, SM1_TOT * 4>>>(x, W1, b1, W2, b2, Wih, bih);
    // Phase 2: GRU
    gru_kernel<<<128, 384>>>(Whh, bhh, out);
}